// round 9
// baseline (speedup 1.0000x reference)
#include <cuda_runtime.h>
#include <math.h>
#include <stdint.h>

#define N_PTS   32768
#define M_CENT  2048
#define K_NB    32
#define D_IN    64
#define D0      67
#define H1DIM   64
#define H2DIM   128
#define RAD2    0.25f

typedef unsigned long long ull;

// ---------------- device scratch (no allocation allowed) ----------------
__device__ float d_sx[N_PTS];
__device__ float d_sy[N_PTS];
__device__ float d_sz[N_PTS];
__device__ int   d_gidx[M_CENT * K_NB];

__device__ __forceinline__ uint32_t smem_u32(const void* p) {
    uint32_t a;
    asm("{ .reg .u64 t; cvta.to.shared.u64 t, %1; cvt.u32.u64 %0, t; }"
        : "=r"(a) : "l"(p));
    return a;
}
__device__ __forceinline__ ull pk2(float lo, float hi) {
    ull r; asm("mov.b64 %0, {%1, %2};" : "=l"(r) : "f"(lo), "f"(hi)); return r;
}
__device__ __forceinline__ void up2(ull v, float& lo, float& hi) {
    asm("mov.b64 {%0, %1}, %2;" : "=f"(lo), "=f"(hi) : "l"(v));
}
#define ADDX2(o, a, b) asm("add.rn.f32x2 %0, %1, %2;" : "=l"(o) : "l"(a), "l"(b))
#define MULX2(o, a, b) asm("mul.rn.f32x2 %0, %1, %2;" : "=l"(o) : "l"(a), "l"(b))

// ---------------- kernel 1: FPS (with integrated AoS->SoA transpose) ----------------
#define FPS_CTAS 8
#define FPS_T    512
#define NW       (FPS_T / 32)          // 16 warps
#define PPC      (N_PTS / FPS_CTAS)    // 4096
#define PPT      (PPC / FPS_T)         // 8
#define PRS      (PPT / 2)             // 4 packed pairs
#define SLOT_BYTES 32                  // key | pad | cxy | cz (cxy 16B-aligned)
#define EXPECT_TX  (FPS_CTAS * 24)     // 3 x 8B actually sent per CTA

// dynamic smem layout (bytes)
#define SM_X     0
#define SM_Y     (SM_X + PPC * 4)
#define SM_Z     (SM_Y + PPC * 4)
#define SM_SLOT  (SM_Z + PPC * 4)
#define SM_MBAR  (SM_SLOT + 2 * FPS_CTAS * SLOT_BYTES)
#define SM_PD    (SM_MBAR + 16)
#define SM_PI    (SM_PD + NW * 4)
#define FPS_SMEM (SM_PI + NW * 4)

__device__ __forceinline__ void mbar_wait(uint32_t mbar, uint32_t parity) {
    asm volatile(
        "{\n\t"
        ".reg .pred P;\n\t"
        "WAIT_%=:\n\t"
        "mbarrier.try_wait.parity.acquire.cta.shared::cta.b64 P, [%0], %1, 0x989680;\n\t"
        "@P bra DONE_%=;\n\t"
        "bra WAIT_%=;\n\t"
        "DONE_%=:\n\t"
        "}"
        :: "r"(mbar), "r"(parity) : "memory");
}

__global__ void __cluster_dims__(FPS_CTAS, 1, 1) __launch_bounds__(FPS_T, 1)
fps_kernel(const float* __restrict__ xyz, float* __restrict__ new_xyz) {
    extern __shared__ __align__(16) unsigned char smraw[];
    float*    s_x  = (float*)(smraw + SM_X);
    float*    s_y  = (float*)(smraw + SM_Y);
    float*    s_z  = (float*)(smraw + SM_Z);
    ull*      s_slot = (ull*)(smraw + SM_SLOT);  // stride 4 ull per (buf,rank)
    unsigned* s_pd = (unsigned*)(smraw + SM_PD);
    unsigned* s_pi = (unsigned*)(smraw + SM_PI);

    const int t    = threadIdx.x;
    const int lane = t & 31;
    const int w    = t >> 5;
    const int cr   = blockIdx.x;  // grid == cluster
    const uint32_t slot_base = smem_u32(smraw + SM_SLOT);
    const uint32_t mbar_base = smem_u32(smraw + SM_MBAR);

    if (t == 0) {
        asm volatile("mbarrier.init.shared.b64 [%0], 1;" :: "r"(mbar_base) : "memory");
        asm volatile("mbarrier.init.shared.b64 [%0], 1;" :: "r"(mbar_base + 8) : "memory");
        // pre-post expected bytes for the first phase of both buffers
        asm volatile("mbarrier.arrive.expect_tx.shared.b64 _, [%0], %1;"
                     :: "r"(mbar_base), "r"((uint32_t)EXPECT_TX) : "memory");
        asm volatile("mbarrier.arrive.expect_tx.shared.b64 _, [%0], %1;"
                     :: "r"(mbar_base + 8), "r"((uint32_t)EXPECT_TX) : "memory");
    }

    // integrated transpose: this CTA's slice AoS -> SMEM mirror + global SoA
    for (int p = t; p < PPC; p += FPS_T) {
        int g = cr * PPC + p;
        float x = xyz[3 * g + 0];
        float y = xyz[3 * g + 1];
        float z = xyz[3 * g + 2];
        s_x[p] = x; s_y[p] = y; s_z[p] = z;
        d_sx[g] = x; d_sy[g] = y; d_sz[g] = z;   // for bq/mlp kernels
    }
    // cluster-wide: mbarrier init visible before any st.async targets it
    asm volatile("barrier.cluster.arrive.aligned;" ::: "memory");
    asm volatile("barrier.cluster.wait.aligned;" ::: "memory");
    __syncthreads();   // SMEM mirror ready for register loads

    const int base = cr * PPC + t;
    ull pxp[PRS], pyp[PRS], pzp[PRS];
    float pd[PPT];
#pragma unroll
    for (int j = 0; j < PRS; j++) {
        int l0 = t + (2 * j) * FPS_T;
        int l1 = t + (2 * j + 1) * FPS_T;
        pxp[j] = pk2(s_x[l0], s_x[l1]);
        pyp[j] = pk2(s_y[l0], s_y[l1]);
        pzp[j] = pk2(s_z[l0], s_z[l1]);
        pd[2 * j] = 1e38f; pd[2 * j + 1] = 1e38f;
    }

    // starting centroid = point 0
    float cx = xyz[0], cy = xyz[1], cz = xyz[2];
    int ph0 = 0, ph1 = 0;

    for (int i = 0; i < M_CENT; i++) {
        if (cr == 0 && t == 0) {
            new_xyz[3 * i + 0] = cx;
            new_xyz[3 * i + 1] = cy;
            new_xyz[3 * i + 2] = cz;
        }
        if (i == M_CENT - 1) break;

        // ---- packed distance update; no per-point index bookkeeping ----
        const ull ncx = pk2(-cx, -cx), ncy = pk2(-cy, -cy), ncz = pk2(-cz, -cz);
        float bd = -1.0f;
#pragma unroll
        for (int j = 0; j < PRS; j++) {
            ull dx, dy, dz, xx, yy, zz, s;
            ADDX2(dx, pxp[j], ncx);          // p - c (== p + (-c), exact)
            ADDX2(dy, pyp[j], ncy);
            ADDX2(dz, pzp[j], ncz);
            MULX2(xx, dx, dx);
            MULX2(yy, dy, dy);
            MULX2(zz, dz, dz);
            ADDX2(s, xx, yy);                // (dx^2 + dy^2)
            ADDX2(s, s, zz);                 // + dz^2 (XLA rounding order)
            float s0, s1; up2(s, s0, s1);
            float nd0 = fminf(pd[2 * j], s0);     pd[2 * j] = nd0;
            float nd1 = fminf(pd[2 * j + 1], s1); pd[2 * j + 1] = nd1;
            bd = fmaxf(bd, nd0);
            bd = fmaxf(bd, nd1);
        }

        // ---- warp argmax via redux; index recovered only in winning warp ----
        unsigned rbi;
        {
            unsigned db = __float_as_uint(bd);
            unsigned rb = __reduce_max_sync(0xFFFFFFFFu, db);
            unsigned bi = 0xFFFFFFFFu;
            if (db == rb) {
                // rescan descending so the lowest index writes last (XLA
                // first-max tie-break within the thread)
#pragma unroll
                for (int j = PPT - 1; j >= 0; j--) {
                    if (pd[j] == bd) bi = (unsigned)(base + j * FPS_T);
                }
            }
            rbi = __reduce_min_sync(0xFFFFFFFFu, bi);
            if (lane == 0) { s_pd[w] = rb; s_pi[w] = rbi; }
        }
        __syncthreads();   // also orders prior slot reads before new sends

        const int nb = (i + 1) & 1;
        const uint32_t mb = mbar_base + nb * 8;

        // ---- CTA argmax (warp 0) + parallel DSMEM fan-out (lanes 0..7) ----
        if (w == 0) {
            unsigned db  = (lane < NW) ? s_pd[lane] : 0u;
            unsigned pbi = (lane < NW) ? s_pi[lane] : 0xFFFFFFFFu;
            unsigned rb  = __reduce_max_sync(0xFFFFFFFFu, db);
            unsigned cnd = (db == rb) ? pbi : 0xFFFFFFFFu;
            unsigned rbw = __reduce_min_sync(0xFFFFFFFFu, cnd);

            if (lane < FPS_CTAS) {
                int li = (int)rbw - cr * PPC;        // winner is always local
                float wx = s_x[li], wy = s_y[li], wz = s_z[li];  // broadcast LDS
                ull key = ((ull)rb << 32) | (ull)(0xFFFFFFFFu - rbw);
                ull cxy = pk2(wx, wy);
                ull czz = (ull)__float_as_uint(wz);
                const uint32_t ls = slot_base + (nb * FPS_CTAS + cr) * SLOT_BYTES;
                uint32_t rs, rm;
                asm("mapa.shared::cluster.u32 %0, %1, %2;" : "=r"(rs) : "r"(ls), "r"(lane));
                asm("mapa.shared::cluster.u32 %0, %1, %2;" : "=r"(rm) : "r"(mb), "r"(lane));
                asm volatile("st.async.shared::cluster.mbarrier::complete_tx::bytes.b64 [%0], %1, [%2];"
                             :: "r"(rs), "l"(key), "r"(rm) : "memory");
                asm volatile("st.async.shared::cluster.mbarrier::complete_tx::bytes.b64 [%0], %1, [%2];"
                             :: "r"(rs + 16), "l"(cxy), "r"(rm) : "memory");
                asm volatile("st.async.shared::cluster.mbarrier::complete_tx::bytes.b64 [%0], %1, [%2];"
                             :: "r"(rs + 24), "l"(czz), "r"(rm) : "memory");
            }
        }

        // ---- wait, then tree-reduce the 8 candidate keys locally ----
        int par = nb ? ph1 : ph0;
        mbar_wait(mb, (uint32_t)par);
        if (nb) ph1 ^= 1; else ph0 ^= 1;

        if (t == 0) {   // re-arm this buffer for its next phase (used at i+2)
            asm volatile("mbarrier.arrive.expect_tx.shared.b64 _, [%0], %1;"
                         :: "r"(mb), "r"((uint32_t)EXPECT_TX) : "memory");
        }

        ull kk[FPS_CTAS]; int aa[FPS_CTAS];
#pragma unroll
        for (int r = 0; r < FPS_CTAS; r++) {
            kk[r] = s_slot[(nb * FPS_CTAS + r) * 4];
            aa[r] = r;
        }
#pragma unroll
        for (int s = FPS_CTAS / 2; s > 0; s >>= 1) {
#pragma unroll
            for (int j = 0; j < s; j++) {
                if (kk[j + s] > kk[j]) { kk[j] = kk[j + s]; aa[j] = aa[j + s]; }
            }
        }
        const ulonglong2* cw = reinterpret_cast<const ulonglong2*>(
            &s_slot[(nb * FPS_CTAS + aa[0]) * 4 + 2]);
        ulonglong2 cc = *cw;           // 16B-aligned: {cxy, cz}
        up2(cc.x, cx, cy);
        cz = __uint_as_float((unsigned)(cc.y & 0xFFFFFFFFull));
    }
}

// ---------------- kernel 2: ball query (top-32 smallest within radius) ----------------
#define BQ_T 256
#define CAP  4096

__global__ void __launch_bounds__(BQ_T)
bq_kernel(const float* __restrict__ new_xyz) {
    __shared__ ull list[CAP];
    __shared__ int s_cnt;
    __shared__ ull s_k[BQ_T / 32];
    __shared__ int s_p[BQ_T / 32];

    const int m = blockIdx.x, t = threadIdx.x;
    if (t == 0) s_cnt = 0;
    __syncthreads();

    const float cx = new_xyz[3 * m + 0];
    const float cy = new_xyz[3 * m + 1];
    const float cz = new_xyz[3 * m + 2];

    for (int p = t; p < N_PTS; p += BQ_T) {
        float dx = d_sx[p] - cx;
        float dy = d_sy[p] - cy;
        float dz = d_sz[p] - cz;
        float d2 = __fadd_rn(__fadd_rn(__fmul_rn(dx, dx), __fmul_rn(dy, dy)),
                             __fmul_rn(dz, dz));
        if (d2 <= RAD2) {
            int pos = atomicAdd(&s_cnt, 1);
            if (pos < CAP)
                list[pos] = ((ull)__float_as_uint(d2) << 32) | (ull)(unsigned)p;
        }
    }
    __syncthreads();

    int n = s_cnt;
    if (n > CAP) n = CAP;

    if (n > K_NB) {
        for (int r = 0; r < K_NB; r++) {
            ull k = ~0ull; int pos = -1;
            for (int q = t; q < n; q += BQ_T) {
                ull v = list[q];
                if (v < k) { k = v; pos = q; }
            }
#pragma unroll
            for (int o = 16; o > 0; o >>= 1) {
                ull k2 = __shfl_xor_sync(0xFFFFFFFFu, k, o);
                int p2 = __shfl_xor_sync(0xFFFFFFFFu, pos, o);
                if (k2 < k) { k = k2; pos = p2; }
            }
            if ((t & 31) == 0) { s_k[t >> 5] = k; s_p[t >> 5] = pos; }
            __syncthreads();
            if (t == 0) {
                ull bk = ~0ull; int bp = -1;
#pragma unroll
                for (int w = 0; w < BQ_T / 32; w++)
                    if (s_k[w] < bk) { bk = s_k[w]; bp = s_p[w]; }
                d_gidx[m * K_NB + r] = (int)(bk & 0xFFFFFFFFull);
                list[bp] = ~0ull;
            }
            __syncthreads();
        }
    } else {
        if (t == 0) {
            int w = 0;
            for (int q = 0; q < n; q++)
                d_gidx[m * K_NB + w++] = (int)(list[q] & 0xFFFFFFFFull);
            for (int p = 0; w < K_NB; p++) {
                float dx = d_sx[p] - cx;
                float dy = d_sy[p] - cy;
                float dz = d_sz[p] - cz;
                float d2 = __fadd_rn(__fadd_rn(__fmul_rn(dx, dx), __fmul_rn(dy, dy)),
                                     __fmul_rn(dz, dz));
                if (d2 > RAD2) d_gidx[m * K_NB + w++] = p;
            }
        }
    }
}

// ---------------- kernel 3: grouped MLP + max-pool ----------------
__device__ __forceinline__ float gelu_exact(float x) {
    return 0.5f * x * (1.0f + erff(x * 0.70710678118654752f));
}

#define MLP_T 128

__global__ void __launch_bounds__(MLP_T)
mlp_kernel(const float* __restrict__ xyz,  const float* __restrict__ feat,
           const float* __restrict__ W1,   const float* __restrict__ b1,
           const float* __restrict__ W2,   const float* __restrict__ b2,
           const float* __restrict__ new_xyz, float* __restrict__ pooled) {
    __shared__ __align__(16) float s_g[K_NB * D0];     // [32][67]
    __shared__ __align__(16) float s_h[K_NB * H1DIM];  // [32][64]
    __shared__ int s_idx[K_NB];

    const int m = blockIdx.x, t = threadIdx.x;
    if (t < K_NB) s_idx[t] = d_gidx[m * K_NB + t];
    __syncthreads();

    const float nx = new_xyz[3 * m + 0];
    const float ny = new_xyz[3 * m + 1];
    const float nz = new_xyz[3 * m + 2];

    for (int e = t; e < K_NB * D0; e += MLP_T) {
        int j = e / D0, k = e - j * D0;
        int id = s_idx[j];
        float v;
        if (k < 3) {
            float c = (k == 0) ? nx : (k == 1) ? ny : nz;
            v = xyz[id * 3 + k] - c;
        } else {
            v = feat[id * D_IN + (k - 3)];
        }
        s_g[j * D0 + k] = v;
    }
    __syncthreads();

    // layer 1: row j = t&31, 16 channels per thread, vectorized W1 loads
    {
        const int j = t & 31, grp = t >> 5;
        float acc[16];
        const float4* bv = reinterpret_cast<const float4*>(&b1[grp * 16]);
#pragma unroll
        for (int q = 0; q < 4; q++) {
            float4 b4 = __ldg(&bv[q]);
            acc[q * 4 + 0] = b4.x; acc[q * 4 + 1] = b4.y;
            acc[q * 4 + 2] = b4.z; acc[q * 4 + 3] = b4.w;
        }
        for (int k = 0; k < D0; k++) {
            float gk = s_g[j * D0 + k];
            const float4* wv = reinterpret_cast<const float4*>(&W1[k * H1DIM + grp * 16]);
#pragma unroll
            for (int q = 0; q < 4; q++) {
                float4 w4 = __ldg(&wv[q]);
                acc[q * 4 + 0] = fmaf(gk, w4.x, acc[q * 4 + 0]);
                acc[q * 4 + 1] = fmaf(gk, w4.y, acc[q * 4 + 1]);
                acc[q * 4 + 2] = fmaf(gk, w4.z, acc[q * 4 + 2]);
                acc[q * 4 + 3] = fmaf(gk, w4.w, acc[q * 4 + 3]);
            }
        }
#pragma unroll
        for (int cc = 0; cc < 16; cc++)
            s_h[j * H1DIM + grp * 16 + cc] = gelu_exact(acc[cc]);
    }
    __syncthreads();

    // layer 2 + max-pool: thread t == output channel, 8-row register tile
    {
        float pm = -3.4e38f;
        const float bb = __ldg(&b2[t]);
        for (int j0 = 0; j0 < K_NB; j0 += 8) {
            float acc[8];
#pragma unroll
            for (int r = 0; r < 8; r++) acc[r] = bb;
            for (int k4 = 0; k4 < H1DIM / 4; k4++) {
                float w0 = __ldg(&W2[(k4 * 4 + 0) * H2DIM + t]);
                float w1 = __ldg(&W2[(k4 * 4 + 1) * H2DIM + t]);
                float w2 = __ldg(&W2[(k4 * 4 + 2) * H2DIM + t]);
                float w3 = __ldg(&W2[(k4 * 4 + 3) * H2DIM + t]);
#pragma unroll
                for (int r = 0; r < 8; r++) {
                    float4 v = *reinterpret_cast<const float4*>(
                        &s_h[(j0 + r) * H1DIM + k4 * 4]);
                    acc[r] = fmaf(v.x, w0, acc[r]);
                    acc[r] = fmaf(v.y, w1, acc[r]);
                    acc[r] = fmaf(v.z, w2, acc[r]);
                    acc[r] = fmaf(v.w, w3, acc[r]);
                }
            }
#pragma unroll
            for (int r = 0; r < 8; r++)
                pm = fmaxf(pm, gelu_exact(acc[r]));
        }
        pooled[m * H2DIM + t] = pm;
    }
}

// ---------------- launch ----------------
extern "C" void kernel_launch(void* const* d_in, const int* in_sizes, int n_in,
                              void* d_out, int out_size) {
    const float* xyz  = (const float*)d_in[0];
    const float* feat = (const float*)d_in[1];
    const float* W1   = (const float*)d_in[2];
    const float* b1   = (const float*)d_in[3];
    const float* W2   = (const float*)d_in[4];
    const float* b2   = (const float*)d_in[5];

    float* out     = (float*)d_out;
    float* new_xyz = out;                 // [2048, 3]
    float* pooled  = out + M_CENT * 3;    // [2048, 128]

    cudaFuncSetAttribute(fps_kernel, cudaFuncAttributeMaxDynamicSharedMemorySize,
                         FPS_SMEM);

    fps_kernel<<<FPS_CTAS, FPS_T, FPS_SMEM>>>(xyz, new_xyz);
    bq_kernel<<<M_CENT, BQ_T>>>(new_xyz);
    mlp_kernel<<<M_CENT, MLP_T>>>(xyz, feat, W1, b1, W2, b2, new_xyz, pooled);
}

// round 10
// speedup vs baseline: 1.7243x; 1.7243x over previous
#include <cuda_runtime.h>
#include <math.h>
#include <stdint.h>

#define N_PTS   32768
#define M_CENT  2048
#define K_NB    32
#define D_IN    64
#define D0      67
#define H1DIM   64
#define H2DIM   128
#define RAD2    0.25f

typedef unsigned long long ull;

// ---------------- device scratch (no allocation allowed) ----------------
__device__ float d_sx[N_PTS];
__device__ float d_sy[N_PTS];
__device__ float d_sz[N_PTS];
__device__ int   d_gidx[M_CENT * K_NB];

__device__ __forceinline__ uint32_t smem_u32(const void* p) {
    uint32_t a;
    asm("{ .reg .u64 t; cvta.to.shared.u64 t, %1; cvt.u32.u64 %0, t; }"
        : "=r"(a) : "l"(p));
    return a;
}
__device__ __forceinline__ ull pk2(float lo, float hi) {
    ull r; asm("mov.b64 %0, {%1, %2};" : "=l"(r) : "f"(lo), "f"(hi)); return r;
}
__device__ __forceinline__ void up2(ull v, float& lo, float& hi) {
    asm("mov.b64 {%0, %1}, %2;" : "=f"(lo), "=f"(hi) : "l"(v));
}
#define ADDX2(o, a, b) asm("add.rn.f32x2 %0, %1, %2;" : "=l"(o) : "l"(a), "l"(b))
#define MULX2(o, a, b) asm("mul.rn.f32x2 %0, %1, %2;" : "=l"(o) : "l"(a), "l"(b))

// ---------------- kernel 1: FPS (with integrated AoS->SoA transpose) ----------------
#define FPS_CTAS 8
#define FPS_T    512
#define NW       (FPS_T / 32)          // 16 warps
#define PPC      (N_PTS / FPS_CTAS)    // 4096
#define PPT      (PPC / FPS_T)         // 8
#define PRS      (PPT / 2)             // 4 packed pairs
#define SLOT_BYTES 32                  // key | pad | cxy | cz (cxy 16B-aligned)
#define EXPECT_TX  (FPS_CTAS * 24)     // 3 x 8B actually sent per CTA

// dynamic smem layout (bytes)
#define SM_X     0
#define SM_Y     (SM_X + PPC * 4)
#define SM_Z     (SM_Y + PPC * 4)
#define SM_SLOT  (SM_Z + PPC * 4)
#define SM_MBAR  (SM_SLOT + 2 * FPS_CTAS * SLOT_BYTES)
#define SM_PD    (SM_MBAR + 16)
#define SM_PI    (SM_PD + NW * 4)
#define FPS_SMEM (SM_PI + NW * 4)

__device__ __forceinline__ void mbar_wait(uint32_t mbar, uint32_t parity) {
    asm volatile(
        "{\n\t"
        ".reg .pred P;\n\t"
        "WAIT_%=:\n\t"
        "mbarrier.try_wait.parity.acquire.cta.shared::cta.b64 P, [%0], %1, 0x989680;\n\t"
        "@P bra DONE_%=;\n\t"
        "bra WAIT_%=;\n\t"
        "DONE_%=:\n\t"
        "}"
        :: "r"(mbar), "r"(parity) : "memory");
}

__global__ void __cluster_dims__(FPS_CTAS, 1, 1) __launch_bounds__(FPS_T, 1)
fps_kernel(const float* __restrict__ xyz, float* __restrict__ new_xyz) {
    extern __shared__ __align__(16) unsigned char smraw[];
    float*    s_x  = (float*)(smraw + SM_X);
    float*    s_y  = (float*)(smraw + SM_Y);
    float*    s_z  = (float*)(smraw + SM_Z);
    ull*      s_slot = (ull*)(smraw + SM_SLOT);  // stride 4 ull per (buf,rank)
    unsigned* s_pd = (unsigned*)(smraw + SM_PD);
    unsigned* s_pi = (unsigned*)(smraw + SM_PI);

    const int t    = threadIdx.x;
    const int lane = t & 31;
    const int w    = t >> 5;
    const int cr   = blockIdx.x;  // grid == cluster
    const uint32_t slot_base = smem_u32(smraw + SM_SLOT);
    const uint32_t mbar_base = smem_u32(smraw + SM_MBAR);

    if (t == 0) {
        asm volatile("mbarrier.init.shared.b64 [%0], 1;" :: "r"(mbar_base) : "memory");
        asm volatile("mbarrier.init.shared.b64 [%0], 1;" :: "r"(mbar_base + 8) : "memory");
        asm volatile("mbarrier.arrive.expect_tx.shared.b64 _, [%0], %1;"
                     :: "r"(mbar_base), "r"((uint32_t)EXPECT_TX) : "memory");
        asm volatile("mbarrier.arrive.expect_tx.shared.b64 _, [%0], %1;"
                     :: "r"(mbar_base + 8), "r"((uint32_t)EXPECT_TX) : "memory");
    }

    // integrated transpose: this CTA's slice AoS -> SMEM mirror + global SoA
    for (int p = t; p < PPC; p += FPS_T) {
        int g = cr * PPC + p;
        float x = xyz[3 * g + 0];
        float y = xyz[3 * g + 1];
        float z = xyz[3 * g + 2];
        s_x[p] = x; s_y[p] = y; s_z[p] = z;
        d_sx[g] = x; d_sy[g] = y; d_sz[g] = z;   // for bq/mlp kernels
    }
    asm volatile("barrier.cluster.arrive.aligned;" ::: "memory");
    asm volatile("barrier.cluster.wait.aligned;" ::: "memory");
    __syncthreads();

    const int base = cr * PPC + t;
    ull pxp[PRS], pyp[PRS], pzp[PRS];
    float pd[PPT];
#pragma unroll
    for (int j = 0; j < PRS; j++) {
        int l0 = t + (2 * j) * FPS_T;
        int l1 = t + (2 * j + 1) * FPS_T;
        pxp[j] = pk2(s_x[l0], s_x[l1]);
        pyp[j] = pk2(s_y[l0], s_y[l1]);
        pzp[j] = pk2(s_z[l0], s_z[l1]);
        pd[2 * j] = 1e38f; pd[2 * j + 1] = 1e38f;
    }

    float cx = xyz[0], cy = xyz[1], cz = xyz[2];
    int ph0 = 0, ph1 = 0;

    for (int i = 0; i < M_CENT; i++) {
        if (cr == 0 && t == 0) {
            new_xyz[3 * i + 0] = cx;
            new_xyz[3 * i + 1] = cy;
            new_xyz[3 * i + 2] = cz;
        }
        if (i == M_CENT - 1) break;

        // ---- packed distance update, track (dist, idx) ----
        const ull ncx = pk2(-cx, -cx), ncy = pk2(-cy, -cy), ncz = pk2(-cz, -cz);
        float bd = -1.0f;
        unsigned bi = 0;
#pragma unroll
        for (int j = 0; j < PRS; j++) {
            ull dx, dy, dz, xx, yy, zz, s;
            ADDX2(dx, pxp[j], ncx);          // p - c (== p + (-c), exact)
            ADDX2(dy, pyp[j], ncy);
            ADDX2(dz, pzp[j], ncz);
            MULX2(xx, dx, dx);
            MULX2(yy, dy, dy);
            MULX2(zz, dz, dz);
            ADDX2(s, xx, yy);                // (dx^2 + dy^2)
            ADDX2(s, s, zz);                 // + dz^2 (XLA rounding order)
            float s0, s1; up2(s, s0, s1);
            float nd0 = fminf(pd[2 * j], s0);     pd[2 * j] = nd0;
            float nd1 = fminf(pd[2 * j + 1], s1); pd[2 * j + 1] = nd1;
            if (nd0 > bd) { bd = nd0; bi = (unsigned)(base + (2 * j) * FPS_T); }
            if (nd1 > bd) { bd = nd1; bi = (unsigned)(base + (2 * j + 1) * FPS_T); }
        }

        // ---- warp argmax via redux ----
        {
            unsigned db  = __float_as_uint(bd);
            unsigned rb  = __reduce_max_sync(0xFFFFFFFFu, db);
            unsigned cnd = (db == rb) ? bi : 0xFFFFFFFFu;
            unsigned rbi = __reduce_min_sync(0xFFFFFFFFu, cnd);
            if (lane == 0) { s_pd[w] = rb; s_pi[w] = rbi; }
        }
        __syncthreads();   // also orders prior slot reads before new sends

        const int nb = (i + 1) & 1;
        const uint32_t mb = mbar_base + nb * 8;

        // ---- CTA argmax (warp 0) + parallel DSMEM fan-out (lanes 0..7) ----
        if (w == 0) {
            unsigned db  = (lane < NW) ? s_pd[lane] : 0u;
            unsigned pbi = (lane < NW) ? s_pi[lane] : 0xFFFFFFFFu;
            unsigned rb  = __reduce_max_sync(0xFFFFFFFFu, db);
            unsigned cnd = (db == rb) ? pbi : 0xFFFFFFFFu;
            unsigned rbw = __reduce_min_sync(0xFFFFFFFFu, cnd);

            if (lane < FPS_CTAS) {
                int li = (int)rbw - cr * PPC;        // winner is always local
                float wx = s_x[li], wy = s_y[li], wz = s_z[li];  // broadcast LDS
                ull key = ((ull)rb << 32) | (ull)(0xFFFFFFFFu - rbw);
                ull cxy = pk2(wx, wy);
                ull czz = (ull)__float_as_uint(wz);
                const uint32_t ls = slot_base + (nb * FPS_CTAS + cr) * SLOT_BYTES;
                uint32_t rs, rm;
                asm("mapa.shared::cluster.u32 %0, %1, %2;" : "=r"(rs) : "r"(ls), "r"(lane));
                asm("mapa.shared::cluster.u32 %0, %1, %2;" : "=r"(rm) : "r"(mb), "r"(lane));
                asm volatile("st.async.shared::cluster.mbarrier::complete_tx::bytes.b64 [%0], %1, [%2];"
                             :: "r"(rs), "l"(key), "r"(rm) : "memory");
                asm volatile("st.async.shared::cluster.mbarrier::complete_tx::bytes.b64 [%0], %1, [%2];"
                             :: "r"(rs + 16), "l"(cxy), "r"(rm) : "memory");
                asm volatile("st.async.shared::cluster.mbarrier::complete_tx::bytes.b64 [%0], %1, [%2];"
                             :: "r"(rs + 24), "l"(czz), "r"(rm) : "memory");
            }
        }

        // ---- wait, then tree-reduce the 8 candidate keys locally ----
        int par = nb ? ph1 : ph0;
        mbar_wait(mb, (uint32_t)par);
        if (nb) ph1 ^= 1; else ph0 ^= 1;

        if (t == 0) {
            asm volatile("mbarrier.arrive.expect_tx.shared.b64 _, [%0], %1;"
                         :: "r"(mb), "r"((uint32_t)EXPECT_TX) : "memory");
        }

        ull kk[FPS_CTAS]; int aa[FPS_CTAS];
#pragma unroll
        for (int r = 0; r < FPS_CTAS; r++) {
            kk[r] = s_slot[(nb * FPS_CTAS + r) * 4];
            aa[r] = r;
        }
#pragma unroll
        for (int s = FPS_CTAS / 2; s > 0; s >>= 1) {
#pragma unroll
            for (int j = 0; j < s; j++) {
                if (kk[j + s] > kk[j]) { kk[j] = kk[j + s]; aa[j] = aa[j + s]; }
            }
        }
        const ulonglong2* cw = reinterpret_cast<const ulonglong2*>(
            &s_slot[(nb * FPS_CTAS + aa[0]) * 4 + 2]);
        ulonglong2 cc = *cw;           // 16B-aligned: {cxy, cz}
        up2(cc.x, cx, cy);
        cz = __uint_as_float((unsigned)(cc.y & 0xFFFFFFFFull));
    }
}

// ---------------- kernel 2: ball query, 2 centroids per block ----------------
#define BQ_T   256
#define BQ_C   2                 // centroids per block
#define CAP2   2048              // per-centroid candidate capacity

__global__ void __launch_bounds__(BQ_T)
bq_kernel(const float* __restrict__ new_xyz) {
    __shared__ ull list[BQ_C * CAP2];
    __shared__ int s_cnt[BQ_C];

    const int m0 = blockIdx.x * BQ_C;
    const int t = threadIdx.x, lane = t & 31, w = t >> 5;

    if (t < BQ_C) s_cnt[t] = 0;
    __syncthreads();

    const float c0x = new_xyz[3 * m0 + 0];
    const float c0y = new_xyz[3 * m0 + 1];
    const float c0z = new_xyz[3 * m0 + 2];
    const float c1x = new_xyz[3 * m0 + 3];
    const float c1y = new_xyz[3 * m0 + 4];
    const float c1z = new_xyz[3 * m0 + 5];

    // scan all points once, test against both centroids
    for (int p = t; p < N_PTS; p += BQ_T) {
        float x = d_sx[p], y = d_sy[p], z = d_sz[p];
        float dx0 = x - c0x, dy0 = y - c0y, dz0 = z - c0z;
        float d20 = __fadd_rn(__fadd_rn(__fmul_rn(dx0, dx0), __fmul_rn(dy0, dy0)),
                              __fmul_rn(dz0, dz0));
        float dx1 = x - c1x, dy1 = y - c1y, dz1 = z - c1z;
        float d21 = __fadd_rn(__fadd_rn(__fmul_rn(dx1, dx1), __fmul_rn(dy1, dy1)),
                              __fmul_rn(dz1, dz1));
        if (d20 <= RAD2) {
            int pos = atomicAdd(&s_cnt[0], 1);
            if (pos < CAP2)
                list[pos] = ((ull)__float_as_uint(d20) << 32) | (ull)(unsigned)p;
        }
        if (d21 <= RAD2) {
            int pos = atomicAdd(&s_cnt[1], 1);
            if (pos < CAP2)
                list[CAP2 + pos] = ((ull)__float_as_uint(d21) << 32) | (ull)(unsigned)p;
        }
    }
    __syncthreads();

    // warp w (0/1) selects top-32 for centroid m0+w, fully warp-local
    if (w < BQ_C) {
        const int m = m0 + w;
        int n = s_cnt[w];
        if (n > CAP2) n = CAP2;
        ull* lst = &list[w * CAP2];

        if (n > K_NB) {
            for (int r = 0; r < K_NB; r++) {
                ull k = ~0ull; int pos = -1;
                for (int q = lane; q < n; q += 32) {
                    ull v = lst[q];
                    if (v < k) { k = v; pos = q; }
                }
#pragma unroll
                for (int o = 16; o > 0; o >>= 1) {
                    ull k2  = __shfl_xor_sync(0xFFFFFFFFu, k, o);
                    int p2  = __shfl_xor_sync(0xFFFFFFFFu, pos, o);
                    if (k2 < k) { k = k2; pos = p2; }
                }
                if (lane == 0) {
                    d_gidx[m * K_NB + r] = (int)(k & 0xFFFFFFFFull);
                    lst[pos] = ~0ull;   // remove winner
                }
                __syncwarp();
            }
        } else if (lane == 0) {
            const float cx = (w == 0) ? c0x : c1x;
            const float cy = (w == 0) ? c0y : c1y;
            const float cz = (w == 0) ? c0z : c1z;
            int o = 0;
            for (int q = 0; q < n; q++)
                d_gidx[m * K_NB + o++] = (int)(lst[q] & 0xFFFFFFFFull);
            for (int p = 0; o < K_NB; p++) {
                float dx = d_sx[p] - cx;
                float dy = d_sy[p] - cy;
                float dz = d_sz[p] - cz;
                float d2 = __fadd_rn(__fadd_rn(__fmul_rn(dx, dx), __fmul_rn(dy, dy)),
                                     __fmul_rn(dz, dz));
                if (d2 > RAD2) d_gidx[m * K_NB + o++] = p;
            }
        }
    }
}

// ---------------- kernel 3: grouped MLP + max-pool ----------------
__device__ __forceinline__ float gelu_exact(float x) {
    return 0.5f * x * (1.0f + erff(x * 0.70710678118654752f));
}

#define MLP_T 128

__global__ void __launch_bounds__(MLP_T)
mlp_kernel(const float* __restrict__ xyz,  const float* __restrict__ feat,
           const float* __restrict__ W1,   const float* __restrict__ b1,
           const float* __restrict__ W2,   const float* __restrict__ b2,
           const float* __restrict__ new_xyz, float* __restrict__ pooled) {
    __shared__ __align__(16) float s_g[K_NB * D0];     // [32][67]
    __shared__ __align__(16) float s_h[K_NB * H1DIM];  // [32][64]
    __shared__ int s_idx[K_NB];

    const int m = blockIdx.x, t = threadIdx.x;
    if (t < K_NB) s_idx[t] = d_gidx[m * K_NB + t];
    __syncthreads();

    const float nx = new_xyz[3 * m + 0];
    const float ny = new_xyz[3 * m + 1];
    const float nz = new_xyz[3 * m + 2];

    for (int e = t; e < K_NB * D0; e += MLP_T) {
        int j = e / D0, k = e - j * D0;
        int id = s_idx[j];
        float v;
        if (k < 3) {
            float c = (k == 0) ? nx : (k == 1) ? ny : nz;
            v = xyz[id * 3 + k] - c;
        } else {
            v = feat[id * D_IN + (k - 3)];
        }
        s_g[j * D0 + k] = v;
    }
    __syncthreads();

    // layer 1: row j = t&31, 16 channels per thread, vectorized W1 loads
    {
        const int j = t & 31, grp = t >> 5;
        float acc[16];
        const float4* bv = reinterpret_cast<const float4*>(&b1[grp * 16]);
#pragma unroll
        for (int q = 0; q < 4; q++) {
            float4 b4 = __ldg(&bv[q]);
            acc[q * 4 + 0] = b4.x; acc[q * 4 + 1] = b4.y;
            acc[q * 4 + 2] = b4.z; acc[q * 4 + 3] = b4.w;
        }
        for (int k = 0; k < D0; k++) {
            float gk = s_g[j * D0 + k];
            const float4* wv = reinterpret_cast<const float4*>(&W1[k * H1DIM + grp * 16]);
#pragma unroll
            for (int q = 0; q < 4; q++) {
                float4 w4 = __ldg(&wv[q]);
                acc[q * 4 + 0] = fmaf(gk, w4.x, acc[q * 4 + 0]);
                acc[q * 4 + 1] = fmaf(gk, w4.y, acc[q * 4 + 1]);
                acc[q * 4 + 2] = fmaf(gk, w4.z, acc[q * 4 + 2]);
                acc[q * 4 + 3] = fmaf(gk, w4.w, acc[q * 4 + 3]);
            }
        }
#pragma unroll
        for (int cc = 0; cc < 16; cc++)
            s_h[j * H1DIM + grp * 16 + cc] = gelu_exact(acc[cc]);
    }
    __syncthreads();

    // layer 2 + max-pool: thread t == output channel, 8-row register tile
    {
        float pm = -3.4e38f;
        const float bb = __ldg(&b2[t]);
        for (int j0 = 0; j0 < K_NB; j0 += 8) {
            float acc[8];
#pragma unroll
            for (int r = 0; r < 8; r++) acc[r] = bb;
            for (int k4 = 0; k4 < H1DIM / 4; k4++) {
                float w0 = __ldg(&W2[(k4 * 4 + 0) * H2DIM + t]);
                float w1 = __ldg(&W2[(k4 * 4 + 1) * H2DIM + t]);
                float w2 = __ldg(&W2[(k4 * 4 + 2) * H2DIM + t]);
                float w3 = __ldg(&W2[(k4 * 4 + 3) * H2DIM + t]);
#pragma unroll
                for (int r = 0; r < 8; r++) {
                    float4 v = *reinterpret_cast<const float4*>(
                        &s_h[(j0 + r) * H1DIM + k4 * 4]);
                    acc[r] = fmaf(v.x, w0, acc[r]);
                    acc[r] = fmaf(v.y, w1, acc[r]);
                    acc[r] = fmaf(v.z, w2, acc[r]);
                    acc[r] = fmaf(v.w, w3, acc[r]);
                }
            }
#pragma unroll
            for (int r = 0; r < 8; r++)
                pm = fmaxf(pm, gelu_exact(acc[r]));
        }
        pooled[m * H2DIM + t] = pm;
    }
}

// ---------------- launch ----------------
extern "C" void kernel_launch(void* const* d_in, const int* in_sizes, int n_in,
                              void* d_out, int out_size) {
    const float* xyz  = (const float*)d_in[0];
    const float* feat = (const float*)d_in[1];
    const float* W1   = (const float*)d_in[2];
    const float* b1   = (const float*)d_in[3];
    const float* W2   = (const float*)d_in[4];
    const float* b2   = (const float*)d_in[5];

    float* out     = (float*)d_out;
    float* new_xyz = out;                 // [2048, 3]
    float* pooled  = out + M_CENT * 3;    // [2048, 128]

    cudaFuncSetAttribute(fps_kernel, cudaFuncAttributeMaxDynamicSharedMemorySize,
                         FPS_SMEM);

    fps_kernel<<<FPS_CTAS, FPS_T, FPS_SMEM>>>(xyz, new_xyz);
    bq_kernel<<<M_CENT / BQ_C, BQ_T>>>(new_xyz);
    mlp_kernel<<<M_CENT, MLP_T>>>(xyz, feat, W1, b1, W2, b2, new_xyz, pooled);
}